// round 1
// baseline (speedup 1.0000x reference)
#include <cuda_runtime.h>
#include <cstdint>

// VDPDropout: mu_out = keep ? mu*1.25 : 0 ; Sigma_out = 1.5625 * Sigma * (nz_i & nz_j)
// B=32, H=2048. Output layout: [mu_out (B*H floats)] then [Sigma_out (B*H*H floats)].

#define B 32
#define H 2048
#define BH (B * H)              // 65536
#define SIGMA_ELEMS ((size_t)BH * H)

__device__ unsigned char g_nz[BH];   // nz = (mu_out != 0), 1 byte each
__device__ int g_mask_kind;          // 0 = int32 {0,1}, 1 = float32 {0,1.0}, 2 = raw bytes

// ---------------------------------------------------------------------------
// Detect the storage dtype of keep_mask. Scans the first 16384 32-bit words,
// which is safe for all candidate dtypes (bytes: 65536B -> 16384 words;
// int32/float32: 262144B -> we only touch the first quarter).
// Deterministic given fixed inputs; re-runs on every graph replay.
// ---------------------------------------------------------------------------
__global__ void detect_mask_kind(const unsigned int* __restrict__ m) {
    __shared__ int s_ok_i32, s_ok_f32;
    if (threadIdx.x == 0) { s_ok_i32 = 1; s_ok_f32 = 1; }
    __syncthreads();
    int ok_i = 1, ok_f = 1;
    for (int i = threadIdx.x; i < 16384; i += blockDim.x) {
        unsigned int w = m[i];
        if (w > 1u) ok_i = 0;
        if (w != 0u && w != 0x3F800000u) ok_f = 0;
    }
    if (!ok_i) atomicAnd(&s_ok_i32, 0);
    if (!ok_f) atomicAnd(&s_ok_f32, 0);
    __syncthreads();
    if (threadIdx.x == 0)
        g_mask_kind = s_ok_i32 ? 0 : (s_ok_f32 ? 1 : 2);
}

// ---------------------------------------------------------------------------
// mu pass: 65536 elements. Writes mu_out and the byte mask g_nz.
// ---------------------------------------------------------------------------
__global__ void mu_kernel(const float* __restrict__ mu,
                          const void* __restrict__ mask,
                          float* __restrict__ mu_out) {
    int i = blockIdx.x * blockDim.x + threadIdx.x;
    if (i >= BH) return;
    int kind = g_mask_kind;
    bool keep;
    if (kind == 0)      keep = ((const int*)mask)[i] != 0;
    else if (kind == 1) keep = ((const float*)mask)[i] != 0.0f;
    else                keep = ((const unsigned char*)mask)[i] != 0;
    float v = keep ? mu[i] * 1.25f : 0.0f;
    mu_out[i] = v;
    g_nz[i] = (v != 0.0f) ? (unsigned char)1 : (unsigned char)0;
}

// ---------------------------------------------------------------------------
// Sigma pass: one block per (b, i) row of 2048 floats.
// 512 threads x float4 = exactly one row. nz row staged in shared (2 KB).
// Pure streaming: 512 MB read + 512 MB write.
// ---------------------------------------------------------------------------
__global__ void __launch_bounds__(512, 4)
sigma_kernel(const float4* __restrict__ Sin, float4* __restrict__ Sout) {
    int r = blockIdx.x;             // r = b*H + i, 0..65535
    int b = r >> 11;
    __shared__ unsigned char snz[H];

    // load this batch's nz row (2048 bytes = 128 x uint4)
    const uint4* nzsrc = reinterpret_cast<const uint4*>(g_nz + ((size_t)b << 11));
    if (threadIdx.x < 128)
        reinterpret_cast<uint4*>(snz)[threadIdx.x] = nzsrc[threadIdx.x];
    __syncthreads();

    // row factor: 0 if row dropped, else scale^2
    float fi = snz[r & (H - 1)] ? 1.5625f : 0.0f;

    const float4* src = Sin + (size_t)r * (H / 4);
    float4*       dst = Sout + (size_t)r * (H / 4);

    int t = threadIdx.x;            // 0..511, exactly H/4 float4s per row
    float4 v = src[t];
    int j = t << 2;
    v.x = snz[j + 0] ? v.x * fi : 0.0f;
    v.y = snz[j + 1] ? v.y * fi : 0.0f;
    v.z = snz[j + 2] ? v.z * fi : 0.0f;
    v.w = snz[j + 3] ? v.w * fi : 0.0f;
    dst[t] = v;
}

// ---------------------------------------------------------------------------
extern "C" void kernel_launch(void* const* d_in, const int* in_sizes, int n_in,
                              void* d_out, int out_size) {
    const float* mu_in    = (const float*)d_in[0];
    const void*  sigma_in = d_in[1];
    const void*  mask     = d_in[2];

    float* mu_out    = (float*)d_out;
    float* sigma_out = (float*)d_out + BH;

    detect_mask_kind<<<1, 1024>>>((const unsigned int*)mask);
    mu_kernel<<<BH / 256, 256>>>(mu_in, mask, mu_out);
    sigma_kernel<<<BH, 512>>>((const float4*)sigma_in, (float4*)sigma_out);
}

// round 2
// speedup vs baseline: 1.0773x; 1.0773x over previous
#include <cuda_runtime.h>
#include <cstdint>

// VDPDropout: mu_out = keep ? mu*1.25 : 0 ; Sigma_out = 1.5625 * Sigma * (nz_i & nz_j)
// B=32, H=2048. Output layout: [mu_out (B*H floats)] then [Sigma_out (B*H*H floats)].

#define B 32
#define H 2048
#define BH (B * H)                  // 65536
#define ROWS_PER_BLK 16             // 16 | 2048 -> block never straddles a batch
#define SIGMA_GRID (BH / ROWS_PER_BLK)

__device__ unsigned char g_nz[BH];  // nz = (mu_out != 0), 1 byte each

// ---------------------------------------------------------------------------
// mu pass with INLINE mask-dtype detection.
// Every block scans the SAME first 256 32-bit words of the mask (1 KB,
// L2-broadcast) and classifies: int32 {0,1} / float32 {0,1.0f} / raw bytes.
// A bytes-mask makes words >1 with P~0.992 per word; a float-mask makes
// words 0x3F800000. 256 words => misclassification probability ~0.
// Deterministic, identical across blocks, re-evaluated every replay.
// ---------------------------------------------------------------------------
__global__ void __launch_bounds__(256)
mu_kernel(const float* __restrict__ mu,
          const unsigned int* __restrict__ mask,
          float* __restrict__ mu_out) {
    unsigned int w = mask[threadIdx.x];          // threadIdx.x in [0,256)
    int bad_i = (w > 1u);
    int bad_f = (w != 0u) & (w != 0x3F800000u);
    int any_bad_i = __syncthreads_or(bad_i);
    int any_bad_f = __syncthreads_or(bad_f);
    int kind = !any_bad_i ? 0 : (!any_bad_f ? 1 : 2);

    int i = blockIdx.x * 256 + threadIdx.x;      // grid = BH/256 blocks
    bool keep;
    if (kind == 0)      keep = ((const int*)mask)[i] != 0;
    else if (kind == 1) keep = ((const float*)mask)[i] != 0.0f;
    else                keep = ((const unsigned char*)mask)[i] != 0;

    float v = keep ? mu[i] * 1.25f : 0.0f;
    mu_out[i] = v;
    g_nz[i] = (v != 0.0f) ? (unsigned char)1 : (unsigned char)0;
}

// ---------------------------------------------------------------------------
// Sigma pass: each block handles ROWS_PER_BLK consecutive rows of one batch.
// nz row staged ONCE per block in shared (2 KB) -> 8 MB total nz traffic.
// 512 threads x 1 float4 = one 2048-float row per iteration; unroll 4 for MLP.
// Pure stream (512 MB in + 512 MB out): __ldcs/__stcs, no reuse.
// ---------------------------------------------------------------------------
__global__ void __launch_bounds__(512)
sigma_kernel(const float4* __restrict__ Sin, float4* __restrict__ Sout) {
    int r0 = blockIdx.x * ROWS_PER_BLK;
    int b  = r0 >> 11;
    __shared__ unsigned char snz[H];

    if (threadIdx.x < 128)
        reinterpret_cast<uint4*>(snz)[threadIdx.x] =
            reinterpret_cast<const uint4*>(g_nz + ((size_t)b << 11))[threadIdx.x];
    __syncthreads();

    int t = threadIdx.x;            // 0..511
    int j = t << 2;
    // per-thread column keep flags (loop-invariant)
    bool c0 = snz[j + 0], c1 = snz[j + 1], c2 = snz[j + 2], c3 = snz[j + 3];

    const float4* src = Sin + (size_t)r0 * (H / 4) + t;
    float4*       dst = Sout + (size_t)r0 * (H / 4) + t;

#pragma unroll 4
    for (int rr = 0; rr < ROWS_PER_BLK; rr++) {
        bool rownz = snz[(r0 + rr) & (H - 1)];
        float4 v = __ldcs(src + (size_t)rr * (H / 4));
        float4 o;
        o.x = (rownz & c0) ? v.x * 1.5625f : 0.0f;
        o.y = (rownz & c1) ? v.y * 1.5625f : 0.0f;
        o.z = (rownz & c2) ? v.z * 1.5625f : 0.0f;
        o.w = (rownz & c3) ? v.w * 1.5625f : 0.0f;
        __stcs(dst + (size_t)rr * (H / 4), o);
    }
}

// ---------------------------------------------------------------------------
extern "C" void kernel_launch(void* const* d_in, const int* in_sizes, int n_in,
                              void* d_out, int out_size) {
    const float* mu_in    = (const float*)d_in[0];
    const void*  sigma_in = d_in[1];
    const void*  mask     = d_in[2];

    float* mu_out    = (float*)d_out;
    float* sigma_out = (float*)d_out + BH;

    mu_kernel<<<BH / 256, 256>>>(mu_in, (const unsigned int*)mask, mu_out);
    sigma_kernel<<<SIGMA_GRID, 512>>>((const float4*)sigma_in, (float4*)sigma_out);
}

// round 3
// speedup vs baseline: 1.1773x; 1.0928x over previous
#include <cuda_runtime.h>
#include <cstdint>

// VDPDropout fused single-kernel:
//   mu_out   = keep ? mu*1.25 : 0                       [B, H]
//   Sigma_out= 1.5625 * Sigma * (nz_i & nz_j)           [B, H, H]
// B=32, H=2048. Output layout: [mu_out (B*H floats)] [Sigma_out (B*H*H floats)].
// Dropped rows (nz_i == 0) are written as zeros WITHOUT reading the input row.

#define B 32
#define H 2048
#define BH (B * H)              // 65536
#define RPB 16                  // rows per block; 16 | 2048 so no batch straddle
#define GRID (BH / RPB)         // 4096

__global__ void __launch_bounds__(512)
fused_kernel(const float* __restrict__ mu,
             const unsigned int* __restrict__ mask,
             float* __restrict__ mu_out,
             const float4* __restrict__ Sin,
             float4* __restrict__ Sout) {
    int r0 = blockIdx.x * RPB;          // first row this block owns
    int b  = r0 >> 11;                  // batch index
    __shared__ unsigned char snz[H];

    // ---- mask dtype detection (identical in every block; L2 broadcast) ----
    // int32 {0,1} / float32 {0,1.0f} / raw bytes. 256 words is decisive.
    unsigned int w = (threadIdx.x < 256) ? mask[threadIdx.x] : 0u;
    int bad_i = (threadIdx.x < 256) && (w > 1u);
    int bad_f = (threadIdx.x < 256) && (w != 0u) && (w != 0x3F800000u);
    int any_bad_i = __syncthreads_or(bad_i);
    int any_bad_f = __syncthreads_or(bad_f);
    int kind = !any_bad_i ? 0 : (!any_bad_f ? 1 : 2);

    // ---- recompute this batch's nz row from mu+mask (L2-resident) ----
    int t = threadIdx.x;                // 0..511, 4 elems each = 2048
    float4 mo;
    unsigned char n0, n1, n2, n3;
    {
        float vq[4];
#pragma unroll
        for (int q = 0; q < 4; q++) {
            int gi = b * H + (t << 2) + q;
            bool keep;
            if (kind == 0)      keep = ((const int*)mask)[gi] != 0;
            else if (kind == 1) keep = ((const float*)mask)[gi] != 0.0f;
            else                keep = ((const unsigned char*)mask)[gi] != 0;
            vq[q] = keep ? mu[gi] * 1.25f : 0.0f;
        }
        mo.x = vq[0]; mo.y = vq[1]; mo.z = vq[2]; mo.w = vq[3];
        n0 = vq[0] != 0.0f; n1 = vq[1] != 0.0f;
        n2 = vq[2] != 0.0f; n3 = vq[3] != 0.0f;
    }
    *reinterpret_cast<uchar4*>(snz + (t << 2)) = make_uchar4(n0, n1, n2, n3);

    // one block per batch (the one owning rows [0,16)) also writes mu_out
    if ((r0 & (H - 1)) == 0)
        reinterpret_cast<float4*>(mu_out)[b * (H / 4) + t] = mo;
    __syncthreads();

    // ---- Sigma stream: 16 rows, skip reads of dropped rows ----
    int j = t << 2;
    bool c0 = snz[j + 0], c1 = snz[j + 1], c2 = snz[j + 2], c3 = snz[j + 3];

    const float4* src = Sin + (size_t)r0 * (H / 4) + t;
    float4*       dst = Sout + (size_t)r0 * (H / 4) + t;
    const float4 zero4 = make_float4(0.f, 0.f, 0.f, 0.f);

#pragma unroll 4
    for (int rr = 0; rr < RPB; rr++) {
        size_t off = (size_t)rr * (H / 4);
        if (snz[(r0 + rr) & (H - 1)]) {      // block-uniform branch
            float4 v = __ldcs(src + off);
            float4 o;
            o.x = c0 ? v.x * 1.5625f : 0.0f;
            o.y = c1 ? v.y * 1.5625f : 0.0f;
            o.z = c2 ? v.z * 1.5625f : 0.0f;
            o.w = c3 ? v.w * 1.5625f : 0.0f;
            __stcs(dst + off, o);
        } else {
            __stcs(dst + off, zero4);        // dropped row: write zeros, no read
        }
    }
}

// ---------------------------------------------------------------------------
extern "C" void kernel_launch(void* const* d_in, const int* in_sizes, int n_in,
                              void* d_out, int out_size) {
    const float* mu_in    = (const float*)d_in[0];
    const void*  sigma_in = d_in[1];
    const void*  mask     = d_in[2];

    float* mu_out    = (float*)d_out;
    float* sigma_out = (float*)d_out + BH;

    fused_kernel<<<GRID, 512>>>(mu_in, (const unsigned int*)mask, mu_out,
                                (const float4*)sigma_in, (float4*)sigma_out);
}